// round 1
// baseline (speedup 1.0000x reference)
#include <cuda_runtime.h>
#include <cuda_bf16.h>
#include <math.h>

#define NN 100000
#define EE 1600000
#define HH 2
#define FF 64
#define DD 256
#define DE 8
#define HF 128           // H*F
#define NEG_SLOPE 0.2f

// ---------------- scratch (device globals; no allocation allowed) ----------
__device__ float g_hsrc[(size_t)NN * HF];
__device__ float g_hdst[(size_t)NN * HF];
__device__ float g_rst [(size_t)NN * HF];
__device__ float g_asrc[(size_t)NN * HH];
__device__ float g_adst[(size_t)NN * HH];
__device__ float g_e   [(size_t)EE * HH];   // logits, then exp()
__device__ float g_m   [(size_t)NN * HH];
__device__ float g_z   [(size_t)NN * HH];

// ---------------- helpers ---------------------------------------------------
__device__ __forceinline__ void atomicMaxFloat(float* addr, float val) {
    // works given init = -inf
    if (val >= 0.0f) {
        atomicMax((int*)addr, __float_as_int(val));
    } else {
        atomicMin((unsigned int*)addr, (unsigned int)__float_as_int(val));
    }
}

__device__ __forceinline__ void red_add_v4(float* addr, float4 v) {
    asm volatile("red.global.add.v4.f32 [%0], {%1,%2,%3,%4};"
                 :: "l"(addr), "f"(v.x), "f"(v.y), "f"(v.z), "f"(v.w)
                 : "memory");
}

// ---------------- init ------------------------------------------------------
__global__ void init_kernel() {
    size_t i = (size_t)blockIdx.x * blockDim.x + threadIdx.x;
    size_t stride = (size_t)gridDim.x * blockDim.x;
    for (size_t k = i; k < (size_t)NN * HF; k += stride) g_rst[k] = 0.0f;
    for (size_t k = i; k < (size_t)NN * HH; k += stride) {
        g_m[k] = -INFINITY;
        g_z[k] = 0.0f;
    }
}

// ---------------- GEMM: C[M,Ncols] = A[M,K] @ B[Ncols,K]^T ------------------
// mode 0: C = acc (+bias if bias!=null)
// mode 1: C = relu(acc + bias) + add   (Ncols must be HF)
__global__ void gemm_nt_kernel(const float* __restrict__ A,
                               const float* __restrict__ B,
                               const float* __restrict__ bias,
                               const float* __restrict__ add,
                               float* __restrict__ C,
                               int M, int Ncols, int K, int mode) {
    const int BM = 64, BN = 64, BK = 16;
    __shared__ float As[BK][BM];
    __shared__ float Bs[BK][BN];

    int bm = blockIdx.y * BM;
    int bn = blockIdx.x * BN;
    int tid = threadIdx.x;              // 256 threads
    int tx = tid & 15;                  // 0..15
    int ty = tid >> 4;                  // 0..15
    int lrow = tid >> 2;                // 0..63
    int lchunk = (tid & 3) * 4;         // 0,4,8,12

    float acc[4][4];
#pragma unroll
    for (int i = 0; i < 4; i++)
#pragma unroll
        for (int j = 0; j < 4; j++) acc[i][j] = 0.0f;

    for (int kt = 0; kt < K; kt += BK) {
        // load A tile (guard M)
        int arow = bm + lrow;
        float4 av = make_float4(0, 0, 0, 0);
        if (arow < M)
            av = *(const float4*)(A + (size_t)arow * K + kt + lchunk);
        As[lchunk + 0][lrow] = av.x;
        As[lchunk + 1][lrow] = av.y;
        As[lchunk + 2][lrow] = av.z;
        As[lchunk + 3][lrow] = av.w;
        // load B tile (Ncols is a multiple of 64 in all uses)
        float4 bv = *(const float4*)(B + (size_t)(bn + lrow) * K + kt + lchunk);
        Bs[lchunk + 0][lrow] = bv.x;
        Bs[lchunk + 1][lrow] = bv.y;
        Bs[lchunk + 2][lrow] = bv.z;
        Bs[lchunk + 3][lrow] = bv.w;
        __syncthreads();

#pragma unroll
        for (int kk = 0; kk < BK; kk++) {
            float4 a4 = *(const float4*)&As[kk][ty * 4];
            float4 b4 = *(const float4*)&Bs[kk][tx * 4];
            float a[4] = {a4.x, a4.y, a4.z, a4.w};
            float b[4] = {b4.x, b4.y, b4.z, b4.w};
#pragma unroll
            for (int i = 0; i < 4; i++)
#pragma unroll
                for (int j = 0; j < 4; j++) acc[i][j] = fmaf(a[i], b[j], acc[i][j]);
        }
        __syncthreads();
    }

#pragma unroll
    for (int i = 0; i < 4; i++) {
        int row = bm + ty * 4 + i;
        if (row >= M) continue;
#pragma unroll
        for (int j = 0; j < 4; j++) {
            int col = bn + tx * 4 + j;
            float v = acc[i][j];
            if (bias) v += bias[col];
            if (mode == 1) {
                v = fmaxf(v, 0.0f) + add[(size_t)row * HF + col];
            }
            C[(size_t)row * Ncols + col] = v;
        }
    }
}

// ---------------- per-node attention logits (a_src, a_dst) -----------------
__global__ void attn_node_kernel(const float* __restrict__ feat,
                                 const float* __restrict__ Wsrc,
                                 const float* __restrict__ Wdst) {
    __shared__ float ws[2 * DD];
    __shared__ float wd[2 * DD];
    for (int i = threadIdx.x; i < 2 * DD; i += blockDim.x) {
        ws[i] = Wsrc[i];
        wd[i] = Wdst[i];
    }
    __syncthreads();

    int gwarp = (blockIdx.x * blockDim.x + threadIdx.x) >> 5;
    int lane = threadIdx.x & 31;
    if (gwarp >= NN) return;

    const float* fp = feat + (size_t)gwarp * DD + lane * 8;
    float4 x0 = *(const float4*)(fp);
    float4 x1 = *(const float4*)(fp + 4);
    float xv[8] = {x0.x, x0.y, x0.z, x0.w, x1.x, x1.y, x1.z, x1.w};

    float s0 = 0, s1 = 0, d0 = 0, d1 = 0;
#pragma unroll
    for (int j = 0; j < 8; j++) {
        int c = lane * 8 + j;
        s0 = fmaf(xv[j], ws[c], s0);
        s1 = fmaf(xv[j], ws[DD + c], s1);
        d0 = fmaf(xv[j], wd[c], d0);
        d1 = fmaf(xv[j], wd[DD + c], d1);
    }
#pragma unroll
    for (int off = 16; off > 0; off >>= 1) {
        s0 += __shfl_xor_sync(0xffffffff, s0, off);
        s1 += __shfl_xor_sync(0xffffffff, s1, off);
        d0 += __shfl_xor_sync(0xffffffff, d0, off);
        d1 += __shfl_xor_sync(0xffffffff, d1, off);
    }
    if (lane == 0) {
        g_asrc[gwarp * 2 + 0] = s0;
        g_asrc[gwarp * 2 + 1] = s1;
        g_adst[gwarp * 2 + 0] = d0;
        g_adst[gwarp * 2 + 1] = d1;
    }
}

// ---------------- edge logits + segment max ---------------------------------
__global__ void edge_logit_kernel(const float* __restrict__ fe,
                                  const int* __restrict__ es,
                                  const int* __restrict__ ed,
                                  const float* __restrict__ Wae) {
    int i = blockIdx.x * blockDim.x + threadIdx.x;
    if (i >= EE) return;

    float4 x0 = *(const float4*)(fe + (size_t)i * DE);
    float4 x1 = *(const float4*)(fe + (size_t)i * DE + 4);

    float ae0 = x0.x * __ldg(&Wae[0]) + x0.y * __ldg(&Wae[1]) +
                x0.z * __ldg(&Wae[2]) + x0.w * __ldg(&Wae[3]) +
                x1.x * __ldg(&Wae[4]) + x1.y * __ldg(&Wae[5]) +
                x1.z * __ldg(&Wae[6]) + x1.w * __ldg(&Wae[7]);
    float ae1 = x0.x * __ldg(&Wae[8])  + x0.y * __ldg(&Wae[9]) +
                x0.z * __ldg(&Wae[10]) + x0.w * __ldg(&Wae[11]) +
                x1.x * __ldg(&Wae[12]) + x1.y * __ldg(&Wae[13]) +
                x1.z * __ldg(&Wae[14]) + x1.w * __ldg(&Wae[15]);

    int s = es[i], d = ed[i];
    float e0 = g_asrc[s * 2 + 0] + g_adst[d * 2 + 0] + ae0;
    float e1 = g_asrc[s * 2 + 1] + g_adst[d * 2 + 1] + ae1;
    e0 = (e0 >= 0.0f) ? e0 : NEG_SLOPE * e0;
    e1 = (e1 >= 0.0f) ? e1 : NEG_SLOPE * e1;
    g_e[(size_t)i * 2 + 0] = e0;
    g_e[(size_t)i * 2 + 1] = e1;
    atomicMaxFloat(&g_m[d * 2 + 0], e0);
    atomicMaxFloat(&g_m[d * 2 + 1], e1);
}

// ---------------- exp + segment sum ------------------------------------------
__global__ void edge_exp_kernel(const int* __restrict__ ed) {
    int i = blockIdx.x * blockDim.x + threadIdx.x;
    if (i >= EE) return;
    int d = ed[i];
    float ex0 = __expf(g_e[(size_t)i * 2 + 0] - g_m[d * 2 + 0]);
    float ex1 = __expf(g_e[(size_t)i * 2 + 1] - g_m[d * 2 + 1]);
    g_e[(size_t)i * 2 + 0] = ex0;
    g_e[(size_t)i * 2 + 1] = ex1;
    atomicAdd(&g_z[d * 2 + 0], ex0);
    atomicAdd(&g_z[d * 2 + 1], ex1);
}

// ---------------- weighted gather/scatter aggregation ------------------------
// one warp per edge; lanes 0..15 head0, lanes 16..31 head1 (4 floats each)
__global__ void edge_agg_kernel(const int* __restrict__ es,
                                const int* __restrict__ ed) {
    int gw = (blockIdx.x * blockDim.x + threadIdx.x) >> 5;
    if (gw >= EE) return;
    int lane = threadIdx.x & 31;

    int s = es[gw], d = ed[gw];
    float ex0 = g_e[(size_t)gw * 2 + 0];
    float ex1 = g_e[(size_t)gw * 2 + 1];
    float c0 = ex0 / g_z[d * 2 + 0];
    float c1 = ex1 / g_z[d * 2 + 1];
    float c = (lane < 16) ? c0 : c1;

    const float4 v = *(const float4*)(g_hsrc + (size_t)s * HF + lane * 4);
    float4 r = make_float4(v.x * c, v.y * c, v.z * c, v.w * c);
    red_add_v4(g_rst + (size_t)d * HF + lane * 4, r);
}

// ---------------- launch -----------------------------------------------------
extern "C" void kernel_launch(void* const* d_in, const int* in_sizes, int n_in,
                              void* d_out, int out_size) {
    const float* feat_src    = (const float*)d_in[0];
    const float* feat_edge   = (const float*)d_in[1];
    const int*   edge_src    = (const int*)d_in[2];
    const int*   edge_dst    = (const int*)d_in[3];
    const float* W_src       = (const float*)d_in[4];
    const float* W_dst       = (const float*)d_in[5];
    const float* b_dst       = (const float*)d_in[6];
    const float* W_attn_src  = (const float*)d_in[7];
    const float* W_attn_dst  = (const float*)d_in[8];
    const float* W_attn_edge = (const float*)d_in[9];
    const float* W_ngnn      = (const float*)d_in[10];
    const float* b_ngnn      = (const float*)d_in[11];
    float* out = (float*)d_out;

    float* hsrc; cudaGetSymbolAddress((void**)&hsrc, g_hsrc);
    float* hdst; cudaGetSymbolAddress((void**)&hdst, g_hdst);
    float* rst;  cudaGetSymbolAddress((void**)&rst,  g_rst);

    // 0. init accumulators
    init_kernel<<<1024, 256>>>();

    // 1. node GEMMs: h_src, h_dst
    dim3 gblk(256);
    dim3 ggrid(HF / 64, (NN + 63) / 64);
    gemm_nt_kernel<<<ggrid, gblk>>>(feat_src, W_src, nullptr, nullptr, hsrc,
                                    NN, HF, DD, 0);
    gemm_nt_kernel<<<ggrid, gblk>>>(feat_src, W_dst, b_dst, nullptr, hdst,
                                    NN, HF, DD, 0);

    // 2. per-node attention logits
    attn_node_kernel<<<(NN * 32 + 255) / 256, 256>>>(feat_src, W_attn_src, W_attn_dst);

    // 3. edge logits + segment max
    edge_logit_kernel<<<(EE + 255) / 256, 256>>>(feat_edge, edge_src, edge_dst, W_attn_edge);

    // 4. exp + segment sum
    edge_exp_kernel<<<(EE + 255) / 256, 256>>>(edge_dst);

    // 5. weighted aggregation (warp per edge)
    edge_agg_kernel<<<(EE * 32 + 255) / 256, 256>>>(edge_src, edge_dst);

    // 6. NGNN GEMM + ReLU + residual -> d_out
    gemm_nt_kernel<<<ggrid, gblk>>>(rst, W_ngnn, b_ngnn, hdst, out,
                                    NN, HF, HF, 1);
}

// round 2
// speedup vs baseline: 1.2945x; 1.2945x over previous
#include <cuda_runtime.h>
#include <math.h>
#include <stdint.h>

#define NN 100000
#define EE 1600000
#define DD 256
#define DE 8
#define HF 128
#define NEG_SLOPE 0.2f

// ---------------- scratch (device globals) ----------------------------------
__device__ float  g_hsrc[(size_t)NN * HF];
__device__ float  g_hdst[(size_t)NN * HF];
__device__ float  g_rst [(size_t)NN * HF];
__device__ float2 g_asrc[NN];
__device__ float2 g_adst[NN];
__device__ float2 g_e   [EE];
__device__ float  g_z   [NN * 2];

// ---------------- f32x2 helpers (FFMA2 — 2x fp32 throughput on sm_103a) -----
static __device__ __forceinline__ unsigned long long pack2(float lo, float hi) {
    unsigned long long r;
    asm("mov.b64 %0, {%1,%2};" : "=l"(r) : "f"(lo), "f"(hi));
    return r;
}
static __device__ __forceinline__ void fma2(unsigned long long& d,
                                            unsigned long long a,
                                            unsigned long long b) {
    asm("fma.rn.f32x2 %0, %1, %2, %0;" : "+l"(d) : "l"(a), "l"(b));
}
static __device__ __forceinline__ float2 unpack2(unsigned long long v) {
    float lo, hi;
    asm("mov.b64 {%0,%1}, %2;" : "=f"(lo), "=f"(hi) : "l"(v));
    return make_float2(lo, hi);
}

static __device__ __forceinline__ void red_add_v4(float* addr, float4 v) {
    asm volatile("red.global.add.v4.f32 [%0], {%1,%2,%3,%4};"
                 :: "l"(addr), "f"(v.x), "f"(v.y), "f"(v.z), "f"(v.w)
                 : "memory");
}

// ---------------- GEMM: C[*,128] = A[M,K] @ B[128,K]^T, FFMA2 microkernel ---
// blockIdx.x selects {B0,bias0,C0} or {B1,bias1,C1}
// mode 0: C = acc (+bias)     mode 1: C = relu(acc+bias) + add
__global__ void __launch_bounds__(256, 2)
gemm_kernel(const float* __restrict__ A,
            const float* __restrict__ B0, const float* __restrict__ B1,
            const float* __restrict__ bias0, const float* __restrict__ bias1,
            const float* __restrict__ add,
            float* __restrict__ C0, float* __restrict__ C1,
            int M, int K, int mode) {
    __shared__ float As[16][132];
    __shared__ float Bs[16][132];

    const float* B    = (blockIdx.x == 0) ? B0 : B1;
    const float* bias = (blockIdx.x == 0) ? bias0 : bias1;
    float*       C    = (blockIdx.x == 0) ? C0 : C1;

    int bm = blockIdx.y * 128;
    int t  = threadIdx.x;
    int tx = t & 15, ty = t >> 4;     // microtile coords
    int lr = t >> 2;                  // 0..63 (load row)
    int lc = (t & 3) * 4;             // 0,4,8,12 (load col chunk)

    unsigned long long acc[8][4];
#pragma unroll
    for (int i = 0; i < 8; i++)
#pragma unroll
        for (int j = 0; j < 4; j++) acc[i][j] = pack2(0.f, 0.f);

    for (int kt = 0; kt < K; kt += 16) {
#pragma unroll
        for (int h = 0; h < 2; h++) {
            int r = lr + h * 64;
            int arow = bm + r;
            float4 av = make_float4(0.f, 0.f, 0.f, 0.f);
            if (arow < M) av = *(const float4*)(A + (size_t)arow * K + kt + lc);
            As[lc + 0][r] = av.x; As[lc + 1][r] = av.y;
            As[lc + 2][r] = av.z; As[lc + 3][r] = av.w;
            float4 bv = *(const float4*)(B + (size_t)r * K + kt + lc);
            Bs[lc + 0][r] = bv.x; Bs[lc + 1][r] = bv.y;
            Bs[lc + 2][r] = bv.z; Bs[lc + 3][r] = bv.w;
        }
        __syncthreads();

#pragma unroll
        for (int kk = 0; kk < 16; kk++) {
            float4 a0 = *(const float4*)&As[kk][ty * 8];
            float4 a1 = *(const float4*)&As[kk][ty * 8 + 4];
            ulonglong2 b01 = *(const ulonglong2*)&Bs[kk][tx * 8];
            ulonglong2 b23 = *(const ulonglong2*)&Bs[kk][tx * 8 + 4];
            float av[8] = {a0.x, a0.y, a0.z, a0.w, a1.x, a1.y, a1.z, a1.w};
#pragma unroll
            for (int i = 0; i < 8; i++) {
                unsigned long long ad = pack2(av[i], av[i]);
                fma2(acc[i][0], ad, b01.x);
                fma2(acc[i][1], ad, b01.y);
                fma2(acc[i][2], ad, b23.x);
                fma2(acc[i][3], ad, b23.y);
            }
        }
        __syncthreads();
    }

    // ---------------- epilogue ----------------
    int cbase = tx * 8;
    float b8[8];
#pragma unroll
    for (int j = 0; j < 8; j++) b8[j] = 0.f;
    if (bias) {
        float4 q0 = *(const float4*)(bias + cbase);
        float4 q1 = *(const float4*)(bias + cbase + 4);
        b8[0] = q0.x; b8[1] = q0.y; b8[2] = q0.z; b8[3] = q0.w;
        b8[4] = q1.x; b8[5] = q1.y; b8[6] = q1.z; b8[7] = q1.w;
    }
#pragma unroll
    for (int i = 0; i < 8; i++) {
        int row = bm + ty * 8 + i;
        if (row >= M) continue;
        float o[8];
#pragma unroll
        for (int j = 0; j < 4; j++) {
            float2 p = unpack2(acc[i][j]);
            o[2 * j]     = p.x + b8[2 * j];
            o[2 * j + 1] = p.y + b8[2 * j + 1];
        }
        if (mode == 1) {
            float4 r0 = *(const float4*)(add + (size_t)row * HF + cbase);
            float4 r1 = *(const float4*)(add + (size_t)row * HF + cbase + 4);
            o[0] = fmaxf(o[0], 0.f) + r0.x; o[1] = fmaxf(o[1], 0.f) + r0.y;
            o[2] = fmaxf(o[2], 0.f) + r0.z; o[3] = fmaxf(o[3], 0.f) + r0.w;
            o[4] = fmaxf(o[4], 0.f) + r1.x; o[5] = fmaxf(o[5], 0.f) + r1.y;
            o[6] = fmaxf(o[6], 0.f) + r1.z; o[7] = fmaxf(o[7], 0.f) + r1.w;
        }
        *(float4*)(C + (size_t)row * HF + cbase) =
            make_float4(o[0], o[1], o[2], o[3]);
        *(float4*)(C + (size_t)row * HF + cbase + 4) =
            make_float4(o[4], o[5], o[6], o[7]);
    }
}

// ---------------- per-node attention logits (register weights) --------------
static __device__ __forceinline__ float dot8(float4 x0, float4 x1,
                                             float4 w0, float4 w1) {
    float s = x0.x * w0.x;
    s = fmaf(x0.y, w0.y, s); s = fmaf(x0.z, w0.z, s); s = fmaf(x0.w, w0.w, s);
    s = fmaf(x1.x, w1.x, s); s = fmaf(x1.y, w1.y, s);
    s = fmaf(x1.z, w1.z, s); s = fmaf(x1.w, w1.w, s);
    return s;
}

__global__ void attn_kernel(const float* __restrict__ feat,
                            const float* __restrict__ Was,
                            const float* __restrict__ Wad) {
    int lane = threadIdx.x & 31;
    int warp = (blockIdx.x * blockDim.x + threadIdx.x) >> 5;
    int nwarps = (gridDim.x * blockDim.x) >> 5;
    int cb = lane * 8;

    float4 ws0a = *(const float4*)(Was + cb);
    float4 ws0b = *(const float4*)(Was + cb + 4);
    float4 ws1a = *(const float4*)(Was + DD + cb);
    float4 ws1b = *(const float4*)(Was + DD + cb + 4);
    float4 wd0a = *(const float4*)(Wad + cb);
    float4 wd0b = *(const float4*)(Wad + cb + 4);
    float4 wd1a = *(const float4*)(Wad + DD + cb);
    float4 wd1b = *(const float4*)(Wad + DD + cb + 4);

    for (int n = warp; n < NN; n += nwarps) {
        const float* fp = feat + (size_t)n * DD + cb;
        float4 x0 = *(const float4*)fp;
        float4 x1 = *(const float4*)(fp + 4);
        float s0 = dot8(x0, x1, ws0a, ws0b);
        float s1 = dot8(x0, x1, ws1a, ws1b);
        float d0 = dot8(x0, x1, wd0a, wd0b);
        float d1 = dot8(x0, x1, wd1a, wd1b);
#pragma unroll
        for (int off = 16; off > 0; off >>= 1) {
            s0 += __shfl_xor_sync(0xffffffff, s0, off);
            s1 += __shfl_xor_sync(0xffffffff, s1, off);
            d0 += __shfl_xor_sync(0xffffffff, d0, off);
            d1 += __shfl_xor_sync(0xffffffff, d1, off);
        }
        if (lane == 0) {
            g_asrc[n] = make_float2(s0, s1);
            g_adst[n] = make_float2(d0, d1);
        }
    }
}

// ---------------- fused edge: logit + leaky + exp + segment-sum -------------
// (max-subtraction dropped: softmax is invariant to it; logits are O(|7|))
__global__ void edge_kernel(const float* __restrict__ fe,
                            const int* __restrict__ es,
                            const int* __restrict__ ed,
                            const float* __restrict__ Wae) {
    int i = blockIdx.x * blockDim.x + threadIdx.x;
    if (i >= EE) return;

    float4 x0 = *(const float4*)(fe + (size_t)i * DE);
    float4 x1 = *(const float4*)(fe + (size_t)i * DE + 4);

    float ae0 = x0.x * __ldg(Wae + 0) + x0.y * __ldg(Wae + 1) +
                x0.z * __ldg(Wae + 2) + x0.w * __ldg(Wae + 3) +
                x1.x * __ldg(Wae + 4) + x1.y * __ldg(Wae + 5) +
                x1.z * __ldg(Wae + 6) + x1.w * __ldg(Wae + 7);
    float ae1 = x0.x * __ldg(Wae + 8)  + x0.y * __ldg(Wae + 9) +
                x0.z * __ldg(Wae + 10) + x0.w * __ldg(Wae + 11) +
                x1.x * __ldg(Wae + 12) + x1.y * __ldg(Wae + 13) +
                x1.z * __ldg(Wae + 14) + x1.w * __ldg(Wae + 15);

    int s = es[i], d = ed[i];
    float2 as = g_asrc[s];
    float2 ad = g_adst[d];
    float e0 = as.x + ad.x + ae0;
    float e1 = as.y + ad.y + ae1;
    e0 = (e0 >= 0.f) ? e0 : NEG_SLOPE * e0;
    e1 = (e1 >= 0.f) ? e1 : NEG_SLOPE * e1;
    float ex0 = __expf(e0);
    float ex1 = __expf(e1);
    g_e[i] = make_float2(ex0, ex1);
    atomicAdd(&g_z[2 * d + 0], ex0);
    atomicAdd(&g_z[2 * d + 1], ex1);
}

// ---------------- weighted gather/scatter aggregation -----------------------
__global__ void agg_kernel(const int* __restrict__ es,
                           const int* __restrict__ ed) {
    int gw = (blockIdx.x * blockDim.x + threadIdx.x) >> 5;
    if (gw >= EE) return;
    int lane = threadIdx.x & 31;

    int s = es[gw], d = ed[gw];
    float2 ex = g_e[gw];
    float e = (lane < 16) ? ex.x : ex.y;
    float z = g_z[2 * d + (lane >= 16)];
    float c = __fdividef(e, z);

    const float4 v = *(const float4*)(g_hsrc + (size_t)s * HF + lane * 4);
    red_add_v4(g_rst + (size_t)d * HF + lane * 4,
               make_float4(v.x * c, v.y * c, v.z * c, v.w * c));
}

// ---------------- launch -----------------------------------------------------
extern "C" void kernel_launch(void* const* d_in, const int* in_sizes, int n_in,
                              void* d_out, int out_size) {
    const float* feat_src    = (const float*)d_in[0];
    const float* feat_edge   = (const float*)d_in[1];
    const int*   edge_src    = (const int*)d_in[2];
    const int*   edge_dst    = (const int*)d_in[3];
    const float* W_src       = (const float*)d_in[4];
    const float* W_dst       = (const float*)d_in[5];
    const float* b_dst       = (const float*)d_in[6];
    const float* W_attn_src  = (const float*)d_in[7];
    const float* W_attn_dst  = (const float*)d_in[8];
    const float* W_attn_edge = (const float*)d_in[9];
    const float* W_ngnn      = (const float*)d_in[10];
    const float* b_ngnn      = (const float*)d_in[11];
    float* out = (float*)d_out;

    float* hsrc; cudaGetSymbolAddress((void**)&hsrc, g_hsrc);
    float* hdst; cudaGetSymbolAddress((void**)&hdst, g_hdst);
    float* rst;  cudaGetSymbolAddress((void**)&rst,  g_rst);
    float* zp;   cudaGetSymbolAddress((void**)&zp,   g_z);

    // 0. zero accumulators
    cudaMemsetAsync(rst, 0, (size_t)NN * HF * sizeof(float));
    cudaMemsetAsync(zp,  0, (size_t)NN * 2 * sizeof(float));

    // 1. node GEMMs: h_src & h_dst in one launch (2 col-blocks)
    gemm_kernel<<<dim3(2, (NN + 127) / 128), 256>>>(
        feat_src, W_src, W_dst, nullptr, b_dst, nullptr,
        hsrc, hdst, NN, DD, 0);

    // 2. per-node attention logits
    attn_kernel<<<1024, 256>>>(feat_src, W_attn_src, W_attn_dst);

    // 3. fused edge logits + exp + z
    edge_kernel<<<(EE + 255) / 256, 256>>>(feat_edge, edge_src, edge_dst,
                                           W_attn_edge);

    // 4. weighted aggregation (warp per edge)
    agg_kernel<<<(EE + 7) / 8, 256>>>(edge_src, edge_dst);

    // 5. NGNN GEMM + ReLU + bias + residual -> d_out
    gemm_kernel<<<dim3(1, (NN + 127) / 128), 256>>>(
        rst, W_ngnn, W_ngnn, b_ngnn, b_ngnn, hdst,
        out, out, NN, HF, 1);
}